// round 1
// baseline (speedup 1.0000x reference)
#include <cuda_runtime.h>
#include <math.h>

#define N_NODES 1024
#define D_IN    256
#define H       64
#define C_CHAINS 20
#define L_STEPS 3
#define E_EDGES 16384
#define BT      8
#define TPB     256

// ---------------- scratch (static device globals; no allocation) ----------------
__device__ __align__(16) float g_t1[N_NODES * H];
__device__ __align__(16) float g_ne[N_NODES * H];          // [n][h]
__device__ __align__(16) float g_neT[H * N_NODES];         // [k][n]
__device__ __align__(16) float g_mask[N_NODES];
__device__ __align__(16) float g_S[C_CHAINS * N_NODES * H];   // [c][n][h]
__device__ __align__(16) float g_np[C_CHAINS * H * N_NODES];  // [c][h][n]  (transposed nodes_part)
__device__ __align__(16) float g_final1[N_NODES * H];
__device__ __align__(16) float g_final[N_NODES * H];

// ---------------- prologue ----------------
__global__ void k_mask_zero() {
    int i = blockIdx.x * blockDim.x + threadIdx.x;
    if (i < N_NODES) g_mask[i] = 0.f;
}

__global__ void k_mask_set(const int* __restrict__ edges) {
    int i = blockIdx.x * blockDim.x + threadIdx.x;
    if (i < E_EDGES) g_mask[edges[2 * i + 1]] = 1.0f;
}

// t1 = relu(nf @ Wt1 + bt1)   [1024,256]@[256,64]
__global__ void k_mlp1(const float* __restrict__ A, const float* __restrict__ W,
                       const float* __restrict__ b) {
    int idx = blockIdx.x * blockDim.x + threadIdx.x;   // over N*H
    int n = idx >> 6, j = idx & 63;
    float acc = b[j];
    #pragma unroll 8
    for (int k = 0; k < D_IN; k++) acc = fmaf(A[n * D_IN + k], W[k * H + j], acc);
    g_t1[idx] = fmaxf(acc, 0.f);
}

// ne = relu(t1 @ Wt2 + bt2)   [1024,64]@[64,64]
__global__ void k_mlp2(const float* __restrict__ W, const float* __restrict__ b) {
    int idx = blockIdx.x * blockDim.x + threadIdx.x;
    int n = idx >> 6, j = idx & 63;
    float acc = b[j];
    #pragma unroll 8
    for (int k = 0; k < H; k++) acc = fmaf(g_t1[n * H + k], W[k * H + j], acc);
    g_ne[idx] = fmaxf(acc, 0.f);
}

// S[c][n][h] = sum_k ne[n,k] * Wci[k, c*H+h] + bci[c*H+h]
__global__ void k_states0(const float* __restrict__ Wci, const float* __restrict__ bci) {
    int idx = blockIdx.x * blockDim.x + threadIdx.x;   // (c*N+n)*H+h
    int h = idx & 63;
    int n = (idx >> 6) & (N_NODES - 1);
    int c = idx >> 16;
    float acc = bci[c * H + h];
    #pragma unroll 8
    for (int k = 0; k < H; k++)
        acc = fmaf(g_ne[n * H + k], Wci[k * (C_CHAINS * H) + c * H + h], acc);
    g_S[idx] = acc;
}

__global__ void k_neT() {
    int idx = blockIdx.x * blockDim.x + threadIdx.x;   // k*1024+n
    int k = idx >> 10, n = idx & (N_NODES - 1);
    g_neT[idx] = g_ne[n * H + k];
}

// npT[c][h][n] = sum_k ne[n,k] * Wa1[c, H+k, h]
__global__ void k_npT(const float* __restrict__ Wa1) {
    int idx = blockIdx.x * blockDim.x + threadIdx.x;   // (c*H+h)*N + n
    int n = idx & (N_NODES - 1);
    int ch = idx >> 10;
    int h = ch & 63, c = ch >> 6;
    const float* W = Wa1 + c * 2 * H * H + H * H;      // w_nodes[k][h]
    float acc = 0.f;
    #pragma unroll 8
    for (int k = 0; k < H; k++)
        acc = fmaf(g_neT[k * N_NODES + n], W[k * H + h], acc);
    g_np[idx] = acc;
}

// ---------------- main fused chain kernel ----------------
// One block = (chain c, 8 state rows). Runs all L=3 steps fused:
// pre -> scores(+mask) -> softmax -> ctx -> GRU update. In-place row-local scan.
__global__ void __launch_bounds__(TPB) k_chain(
    const float* __restrict__ Wa1, const float* __restrict__ ba1,
    const float* __restrict__ Wa2, const float* __restrict__ ba2,
    const float* __restrict__ Wih, const float* __restrict__ Whh,
    const float* __restrict__ bih, const float* __restrict__ bhh,
    float* __restrict__ out_stk)
{
    const int c = blockIdx.y;
    const int b0 = blockIdx.x * BT;
    const int tid = threadIdx.x;

    __shared__ float s_sc[BT][N_NODES];   // 32 KB: scores / exp-weights
    __shared__ float s_s[BT][H];
    __shared__ float s_pre[BT][H];
    __shared__ float s_ctx[BT][H];
    __shared__ float s_net[32][H];        // 8 KB ne tile
    __shared__ float s_wa2v[H];
    __shared__ float s_ba1v[H];
    __shared__ float s_inv[BT];

    if (tid < H) { s_wa2v[tid] = Wa2[c * H + tid]; s_ba1v[tid] = ba1[c * H + tid]; }
    const float ba2c = ba2[c];
    for (int i = tid; i < BT * H; i += TPB) {
        int bi = i >> 6, h = i & 63;
        s_s[bi][h] = g_S[((size_t)c * N_NODES + b0 + bi) * H + h];
    }
    __syncthreads();

    const float* npT = g_np + (size_t)c * H * N_NODES;
    const float* wstate = Wa1 + (size_t)c * 2 * H * H;  // [k][h]
    const float* wi_base = Wih + (size_t)c * 3 * H * H;
    const float* wh_base = Whh + (size_t)c * 3 * H * H;

    for (int t = 0; t < L_STEPS; t++) {
        // ---- pre = s @ w_state + ba1 ----
        for (int i = tid; i < BT * H; i += TPB) {
            int bi = i >> 6, h = i & 63;
            float acc = s_ba1v[h];
            #pragma unroll 8
            for (int k = 0; k < H; k++)
                acc = fmaf(s_s[bi][k], __ldg(&wstate[k * H + h]), acc);
            s_pre[bi][h] = acc;
        }
        __syncthreads();

        // ---- scores[bi][n] = (sum_h wa2[h]*relu(pre+np) + ba2) * mask[n] ----
        {
            float acc[BT][4];
            #pragma unroll
            for (int bi = 0; bi < BT; bi++) {
                acc[bi][0] = 0.f; acc[bi][1] = 0.f; acc[bi][2] = 0.f; acc[bi][3] = 0.f;
            }
            const int n0 = tid * 4;
            #pragma unroll 2
            for (int h = 0; h < H; h++) {
                const float w = s_wa2v[h];
                const float4 v = __ldg((const float4*)(npT + (size_t)h * N_NODES + n0));
                #pragma unroll
                for (int bi = 0; bi < BT; bi++) {
                    const float p = s_pre[bi][h];
                    acc[bi][0] = fmaf(w, fmaxf(p + v.x, 0.f), acc[bi][0]);
                    acc[bi][1] = fmaf(w, fmaxf(p + v.y, 0.f), acc[bi][1]);
                    acc[bi][2] = fmaf(w, fmaxf(p + v.z, 0.f), acc[bi][2]);
                    acc[bi][3] = fmaf(w, fmaxf(p + v.w, 0.f), acc[bi][3]);
                }
            }
            const float4 m4 = *(const float4*)(g_mask + n0);
            #pragma unroll
            for (int bi = 0; bi < BT; bi++) {
                float4 r;
                r.x = (acc[bi][0] + ba2c) * m4.x;
                r.y = (acc[bi][1] + ba2c) * m4.y;
                r.z = (acc[bi][2] + ba2c) * m4.z;
                r.w = (acc[bi][3] + ba2c) * m4.w;
                *(float4*)&s_sc[bi][n0] = r;
            }
        }
        __syncthreads();

        // ---- row softmax (store unnormalized exp, keep 1/sum) ----
        {
            const int wid = tid >> 5, lane = tid & 31;  // warp wid owns row wid
            float mx = -1e30f;
            for (int n = lane; n < N_NODES; n += 32) mx = fmaxf(mx, s_sc[wid][n]);
            #pragma unroll
            for (int o = 16; o > 0; o >>= 1) mx = fmaxf(mx, __shfl_xor_sync(0xffffffffu, mx, o));
            float sm = 0.f;
            for (int n = lane; n < N_NODES; n += 32) {
                float p = expf(s_sc[wid][n] - mx);
                s_sc[wid][n] = p;
                sm += p;
            }
            #pragma unroll
            for (int o = 16; o > 0; o >>= 1) sm += __shfl_xor_sync(0xffffffffu, sm, o);
            if (lane == 0) s_inv[wid] = 1.f / sm;
        }
        __syncthreads();

        // ---- ctx = (w @ ne) * inv, smem-tiled over n ----
        {
            const int bi0 = tid >> 6;   // 0..3, pairs (bi0, bi0+4)
            const int h = tid & 63;
            float a0 = 0.f, a1 = 0.f;
            for (int tile = 0; tile < N_NODES / 32; tile++) {
                #pragma unroll
                for (int v = 0; v < 2; v++) {
                    int ii = tid + v * 256;
                    int row = ii >> 4, cc = (ii & 15) * 4;
                    *(float4*)&s_net[row][cc] =
                        *(const float4*)&g_ne[(tile * 32 + row) * H + cc];
                }
                __syncthreads();
                const int nb = tile * 32;
                #pragma unroll 8
                for (int nn = 0; nn < 32; nn++) {
                    const float nev = s_net[nn][h];
                    a0 = fmaf(s_sc[bi0    ][nb + nn], nev, a0);
                    a1 = fmaf(s_sc[bi0 + 4][nb + nn], nev, a1);
                }
                __syncthreads();
            }
            s_ctx[bi0][h]     = a0 * s_inv[bi0];
            s_ctx[bi0 + 4][h] = a1 * s_inv[bi0 + 4];
        }
        __syncthreads();

        // ---- GRU gates + update ----
        {
            float news[2];
            #pragma unroll
            for (int p = 0; p < 2; p++) {
                int i = tid + p * 256;
                int bi = i >> 6, h = i & 63;
                const float* wi = wi_base + (size_t)h * H;
                const float* wh = wh_base + (size_t)h * H;
                float gir = 0.f, giz = 0.f, gic = 0.f, ghr = 0.f, ghz = 0.f, ghc = 0.f;
                #pragma unroll 4
                for (int k4 = 0; k4 < H / 4; k4++) {
                    float4 cv = *(const float4*)&s_ctx[bi][k4 * 4];
                    float4 sv = *(const float4*)&s_s[bi][k4 * 4];
                    float4 a  = __ldg((const float4*)(wi + k4 * 4));
                    float4 b1 = __ldg((const float4*)(wi + H * H + k4 * 4));
                    float4 b2 = __ldg((const float4*)(wi + 2 * H * H + k4 * 4));
                    float4 d0 = __ldg((const float4*)(wh + k4 * 4));
                    float4 d1 = __ldg((const float4*)(wh + H * H + k4 * 4));
                    float4 d2 = __ldg((const float4*)(wh + 2 * H * H + k4 * 4));
                    gir += cv.x * a.x  + cv.y * a.y  + cv.z * a.z  + cv.w * a.w;
                    giz += cv.x * b1.x + cv.y * b1.y + cv.z * b1.z + cv.w * b1.w;
                    gic += cv.x * b2.x + cv.y * b2.y + cv.z * b2.z + cv.w * b2.w;
                    ghr += sv.x * d0.x + sv.y * d0.y + sv.z * d0.z + sv.w * d0.w;
                    ghz += sv.x * d1.x + sv.y * d1.y + sv.z * d1.z + sv.w * d1.w;
                    ghc += sv.x * d2.x + sv.y * d2.y + sv.z * d2.z + sv.w * d2.w;
                }
                gir += bih[c * 3 * H + h];       ghr += bhh[c * 3 * H + h];
                giz += bih[c * 3 * H + 64 + h];  ghz += bhh[c * 3 * H + 64 + h];
                gic += bih[c * 3 * H + 128 + h]; ghc += bhh[c * 3 * H + 128 + h];
                float r = 1.f / (1.f + expf(-(gir + ghr)));
                float z = 1.f / (1.f + expf(-(giz + ghz)));
                float cand = tanhf(gic + r * ghc);
                news[p] = (1.f - z) * cand + z * s_s[bi][h];
            }
            __syncthreads();
            #pragma unroll
            for (int p = 0; p < 2; p++) {
                int i = tid + p * 256;
                s_s[i >> 6][i & 63] = news[p];
            }
        }
        __syncthreads();
    }

    for (int i = tid; i < BT * H; i += TPB) {
        int bi = i >> 6, h = i & 63;
        int n = b0 + bi;
        float v = s_s[bi][h];
        g_S[((size_t)c * N_NODES + n) * H + h] = v;
        out_stk[((size_t)n * C_CHAINS + c) * H + h] = v;
    }
}

// ---------------- epilogue ----------------
// final1 = relu(concat @ Wag1 + bag1), concat[n, c*H+h] = S[c][n][h]
__global__ void k_final1(const float* __restrict__ Wag1, const float* __restrict__ bag1) {
    int idx = blockIdx.x * blockDim.x + threadIdx.x;   // n*64+j
    int n = idx >> 6, j = idx & 63;
    float acc = bag1[j];
    for (int c = 0; c < C_CHAINS; c++) {
        const float* Sr = g_S + ((size_t)c * N_NODES + n) * H;
        const float* Wr = Wag1 + (size_t)c * H * H + j;
        #pragma unroll 8
        for (int h = 0; h < H; h++)
            acc = fmaf(Sr[h], Wr[(size_t)h * H], acc);
    }
    g_final1[idx] = fmaxf(acc, 0.f);
}

// final = final1 @ Wag2 + bag2 (no relu)
__global__ void k_final2(const float* __restrict__ Wag2, const float* __restrict__ bag2,
                         float* __restrict__ o_fin) {
    int idx = blockIdx.x * blockDim.x + threadIdx.x;
    int n = idx >> 6, j = idx & 63;
    float acc = bag2[j];
    #pragma unroll 8
    for (int k = 0; k < H; k++)
        acc = fmaf(g_final1[n * H + k], Wag2[k * H + j], acc);
    g_final[idx] = acc;
    o_fin[idx] = acc;
}

// attn = softmax_c(final . S[c]), pred = final @ Wp + bp. One warp per node.
__global__ void k_attn(const float* __restrict__ Wp, const float* __restrict__ bp,
                       float* __restrict__ o_att, float* __restrict__ o_pred) {
    int gw = (blockIdx.x * blockDim.x + threadIdx.x) >> 5;
    int lane = threadIdx.x & 31;
    if (gw >= N_NODES) return;
    int n = gw;
    const float* fv = g_final + n * H;
    float dot = -1e30f;
    if (lane < C_CHAINS) {
        const float* Sv = g_S + ((size_t)lane * N_NODES + n) * H;
        float d = 0.f;
        #pragma unroll 8
        for (int h = 0; h < H; h++) d = fmaf(fv[h], Sv[h], d);
        dot = d;
    }
    float mx = dot;
    #pragma unroll
    for (int o = 16; o > 0; o >>= 1) mx = fmaxf(mx, __shfl_xor_sync(0xffffffffu, mx, o));
    float p = (lane < C_CHAINS) ? expf(dot - mx) : 0.f;
    float sm = p;
    #pragma unroll
    for (int o = 16; o > 0; o >>= 1) sm += __shfl_xor_sync(0xffffffffu, sm, o);
    if (lane < C_CHAINS) o_att[n * C_CHAINS + lane] = p / sm;

    float ps = 0.f;
    for (int h = lane; h < H; h += 32) ps = fmaf(fv[h], Wp[h], ps);
    #pragma unroll
    for (int o = 16; o > 0; o >>= 1) ps += __shfl_xor_sync(0xffffffffu, ps, o);
    if (lane == 0) o_pred[n] = ps + bp[0];
}

// ---------------- launch ----------------
extern "C" void kernel_launch(void* const* d_in, const int* in_sizes, int n_in,
                              void* d_out, int out_size) {
    (void)in_sizes; (void)n_in; (void)out_size;
    const float* nf    = (const float*)d_in[0];
    const int*   edges = (const int*)d_in[1];
    const float* Wt1   = (const float*)d_in[2];
    const float* bt1   = (const float*)d_in[3];
    const float* Wt2   = (const float*)d_in[4];
    const float* bt2   = (const float*)d_in[5];
    const float* Wci   = (const float*)d_in[6];
    const float* bci   = (const float*)d_in[7];
    const float* Wa1   = (const float*)d_in[8];
    const float* ba1   = (const float*)d_in[9];
    const float* Wa2   = (const float*)d_in[10];
    const float* ba2   = (const float*)d_in[11];
    const float* Wih   = (const float*)d_in[12];
    const float* Whh   = (const float*)d_in[13];
    const float* bih   = (const float*)d_in[14];
    const float* bhh   = (const float*)d_in[15];
    const float* Wag1  = (const float*)d_in[16];
    const float* bag1  = (const float*)d_in[17];
    const float* Wag2  = (const float*)d_in[18];
    const float* bag2  = (const float*)d_in[19];
    const float* Wp    = (const float*)d_in[20];
    const float* bp    = (const float*)d_in[21];

    float* out    = (float*)d_out;
    float* o_stk  = out;
    float* o_fin  = out + (size_t)N_NODES * C_CHAINS * H;
    float* o_att  = o_fin + N_NODES * H;
    float* o_pred = o_att + N_NODES * C_CHAINS;

    k_mask_zero<<<N_NODES / 256, 256>>>();
    k_mask_set<<<E_EDGES / 256, 256>>>(edges);
    k_mlp1<<<(N_NODES * H) / 256, 256>>>(nf, Wt1, bt1);
    k_mlp2<<<(N_NODES * H) / 256, 256>>>(Wt2, bt2);
    k_states0<<<(C_CHAINS * N_NODES * H) / 256, 256>>>(Wci, bci);
    k_neT<<<(N_NODES * H) / 256, 256>>>();
    k_npT<<<(C_CHAINS * H * N_NODES) / 256, 256>>>(Wa1);

    dim3 grid(N_NODES / BT, C_CHAINS);
    k_chain<<<grid, TPB>>>(Wa1, ba1, Wa2, ba2, Wih, Whh, bih, bhh, o_stk);

    k_final1<<<(N_NODES * H) / 256, 256>>>(Wag1, bag1);
    k_final2<<<(N_NODES * H) / 256, 256>>>(Wag2, bag2, o_fin);
    k_attn<<<N_NODES / 8, 256>>>(Wp, bp, o_att, o_pred);
}

// round 2
// speedup vs baseline: 3.0154x; 3.0154x over previous
#include <cuda_runtime.h>
#include <math.h>

#define N_NODES 1024
#define D_IN    256
#define H       64
#define C_CHAINS 20
#define L_STEPS 3
#define E_EDGES 16384
#define BT      8
#define TPB     256

// ---------------- scratch (static device globals; no allocation) ----------------
__device__ __align__(16) float g_t1[N_NODES * H];
__device__ __align__(16) float g_ne[N_NODES * H];          // [n][h]
__device__ __align__(16) float g_neT[H * N_NODES];         // [k][n]
__device__ __align__(16) float g_mask[N_NODES];
__device__ __align__(16) float g_S[C_CHAINS * N_NODES * H];   // [c][n][h]
__device__ __align__(16) float g_np[C_CHAINS * H * N_NODES];  // [c][h][n]
__device__ __align__(16) float g_WihT[C_CHAINS * H * 3 * H];  // [c][k][3H]
__device__ __align__(16) float g_WhhT[C_CHAINS * H * 3 * H];  // [c][k][3H]
__device__ __align__(16) float g_final1[N_NODES * H];
__device__ __align__(16) float g_final[N_NODES * H];

__device__ __forceinline__ float fsigf(float x) {
    return __fdividef(1.f, 1.f + __expf(-x));
}
__device__ __forceinline__ float ftanhf(float x) {
    x = fminf(fmaxf(x, -15.f), 15.f);
    float e = __expf(2.f * x);
    return __fdividef(e - 1.f, e + 1.f);
}

// ---------------- prologue ----------------
__global__ void k_mask_set(const int* __restrict__ edges) {
    int i = blockIdx.x * blockDim.x + threadIdx.x;
    if (i < E_EDGES) g_mask[edges[2 * i + 1]] = 1.0f;
}

// t1 = relu(nf @ Wt1 + bt1); also zero mask
__global__ void k_mlp1(const float* __restrict__ A, const float* __restrict__ W,
                       const float* __restrict__ b) {
    int idx = blockIdx.x * blockDim.x + threadIdx.x;   // over N*H
    if (idx < N_NODES) g_mask[idx] = 0.f;
    int n = idx >> 6, j = idx & 63;
    float acc = b[j];
    #pragma unroll 8
    for (int k = 0; k < D_IN; k++) acc = fmaf(A[n * D_IN + k], W[k * H + j], acc);
    g_t1[idx] = fmaxf(acc, 0.f);
}

// ne = relu(t1 @ Wt2 + bt2); also write neT
__global__ void k_mlp2(const float* __restrict__ W, const float* __restrict__ b) {
    int idx = blockIdx.x * blockDim.x + threadIdx.x;
    int n = idx >> 6, j = idx & 63;
    float acc = b[j];
    #pragma unroll 8
    for (int k = 0; k < H; k++) acc = fmaf(g_t1[n * H + k], W[k * H + j], acc);
    float v = fmaxf(acc, 0.f);
    g_ne[idx] = v;
    g_neT[j * N_NODES + n] = v;
}

// S0[c][n][h] = ne @ Wci + bci
__global__ void k_states0(const float* __restrict__ Wci, const float* __restrict__ bci) {
    int idx = blockIdx.x * blockDim.x + threadIdx.x;   // (c*N+n)*H+h
    int h = idx & 63;
    int n = (idx >> 6) & (N_NODES - 1);
    int c = idx >> 16;
    float acc = bci[c * H + h];
    #pragma unroll 8
    for (int k = 0; k < H; k++)
        acc = fmaf(g_ne[n * H + k], Wci[k * (C_CHAINS * H) + c * H + h], acc);
    g_S[idx] = acc;
}

// npT[c][h][n] = sum_k ne[n,k] * Wa1[c, H+k, h]
__global__ void k_npT(const float* __restrict__ Wa1) {
    int idx = blockIdx.x * blockDim.x + threadIdx.x;   // (c*H+h)*N + n
    int n = idx & (N_NODES - 1);
    int ch = idx >> 10;
    int h = ch & 63, c = ch >> 6;
    const float* W = Wa1 + c * 2 * H * H + H * H;
    float acc = 0.f;
    #pragma unroll 8
    for (int k = 0; k < H; k++)
        acc = fmaf(g_neT[k * N_NODES + n], W[k * H + h], acc);
    g_np[idx] = acc;
}

// WihT[c][k][j] = Wih[c][j][k]; same for Whh.  (j in 0..191)
__global__ void k_gruT(const float* __restrict__ Wih, const float* __restrict__ Whh) {
    int idx = blockIdx.x * blockDim.x + threadIdx.x;   // c*12288 + k*192 + j
    int j = idx % 192;
    int t = idx / 192;
    int k = t & 63, c = t >> 6;
    int src = c * 12288 + j * H + k;
    g_WihT[idx] = Wih[src];
    g_WhhT[idx] = Whh[src];
}

// ---------------- main fused chain kernel ----------------
// block = (chain c, 8 state rows). L=3 steps fused. Dynamic smem 72KB.
__global__ void __launch_bounds__(TPB) k_chain(
    const float* __restrict__ Wa1, const float* __restrict__ ba1,
    const float* __restrict__ Wa2, const float* __restrict__ ba2,
    const float* __restrict__ bih, const float* __restrict__ bhh,
    float* __restrict__ out_stk)
{
    const int c = blockIdx.y;
    const int b0 = blockIdx.x * BT;
    const int tid = threadIdx.x;

    extern __shared__ float sm[];
    float* s_sc  = sm;            // [8][1024] scores / exp weights
    float* s_buf = sm + 8192;     // [128][64] ne tile  | gates gi[8][192], gh[8][192]
    float* s_s   = sm + 16384;    // [8][64]
    float* s_pre = sm + 16896;    // [8][64]
    float* s_ctx = sm + 17408;    // [8][64]
    float* s_wa2 = sm + 17920;    // [64]
    float* s_ba1 = sm + 17984;    // [64]
    float* s_inv = sm + 18048;    // [8]

    if (tid < H) { s_wa2[tid] = Wa2[c * H + tid]; s_ba1[tid] = ba1[c * H + tid]; }
    const float ba2c = ba2[c];
    #pragma unroll
    for (int p = 0; p < 2; p++) {
        int i = tid + p * 256;
        int bi = i >> 6, h = i & 63;
        s_s[i] = g_S[((size_t)c * N_NODES + b0 + bi) * H + h];
    }
    __syncthreads();

    const float* npT = g_np + (size_t)c * H * N_NODES;
    const float* wstate = Wa1 + (size_t)c * 2 * H * H;  // [k][h]
    const float* wiT = g_WihT + (size_t)c * H * 192;
    const float* whT = g_WhhT + (size_t)c * H * 192;

    for (int t = 0; t < L_STEPS; t++) {
        // ---- pre = s @ w_state + ba1 ----
        #pragma unroll
        for (int p = 0; p < 2; p++) {
            int i = tid + p * 256;
            int bi = i >> 6, h = i & 63;
            float acc = s_ba1[h];
            #pragma unroll 8
            for (int k = 0; k < H; k++)
                acc = fmaf(s_s[bi * H + k], __ldg(&wstate[k * H + h]), acc);
            s_pre[i] = acc;
        }
        __syncthreads();

        // ---- scores[bi][n] = (sum_h wa2[h]*relu(pre+np) + ba2) * mask[n] ----
        {
            float acc[BT][4];
            #pragma unroll
            for (int bi = 0; bi < BT; bi++) {
                acc[bi][0] = 0.f; acc[bi][1] = 0.f; acc[bi][2] = 0.f; acc[bi][3] = 0.f;
            }
            const int n0 = tid * 4;
            #pragma unroll 4
            for (int h = 0; h < H; h++) {
                const float w = s_wa2[h];
                const float4 v = __ldg((const float4*)(npT + (size_t)h * N_NODES + n0));
                #pragma unroll
                for (int bi = 0; bi < BT; bi++) {
                    const float p = s_pre[bi * H + h];
                    acc[bi][0] = fmaf(w, fmaxf(p + v.x, 0.f), acc[bi][0]);
                    acc[bi][1] = fmaf(w, fmaxf(p + v.y, 0.f), acc[bi][1]);
                    acc[bi][2] = fmaf(w, fmaxf(p + v.z, 0.f), acc[bi][2]);
                    acc[bi][3] = fmaf(w, fmaxf(p + v.w, 0.f), acc[bi][3]);
                }
            }
            const float4 m4 = *(const float4*)(g_mask + n0);
            #pragma unroll
            for (int bi = 0; bi < BT; bi++) {
                float4 r;
                r.x = (acc[bi][0] + ba2c) * m4.x;
                r.y = (acc[bi][1] + ba2c) * m4.y;
                r.z = (acc[bi][2] + ba2c) * m4.z;
                r.w = (acc[bi][3] + ba2c) * m4.w;
                *(float4*)&s_sc[bi * N_NODES + n0] = r;
            }
        }
        __syncthreads();

        // ---- row softmax (unnormalized exp in place; keep 1/sum) ----
        {
            const int wid = tid >> 5, lane = tid & 31;
            float mx = -1e30f;
            #pragma unroll 4
            for (int n = lane; n < N_NODES; n += 32) mx = fmaxf(mx, s_sc[wid * N_NODES + n]);
            #pragma unroll
            for (int o = 16; o > 0; o >>= 1) mx = fmaxf(mx, __shfl_xor_sync(0xffffffffu, mx, o));
            float smv = 0.f;
            #pragma unroll 4
            for (int n = lane; n < N_NODES; n += 32) {
                float p = __expf(s_sc[wid * N_NODES + n] - mx);
                s_sc[wid * N_NODES + n] = p;
                smv += p;
            }
            #pragma unroll
            for (int o = 16; o > 0; o >>= 1) smv += __shfl_xor_sync(0xffffffffu, smv, o);
            if (lane == 0) s_inv[wid] = __fdividef(1.f, smv);
        }
        __syncthreads();

        // ---- ctx[g][h] = sum_n w[g][n]*ne[n][h], 128-row smem tiles ----
        {
            const int g = tid >> 5;          // warp g owns state row g
            const int h0 = (tid & 31) * 2;
            float a0 = 0.f, a1 = 0.f;
            for (int tile = 0; tile < N_NODES / 128; tile++) {
                #pragma unroll
                for (int v = 0; v < 8; v++) {
                    int slot = tid + v * 256;     // float4 slots 0..2047
                    *(float4*)&s_buf[slot * 4] =
                        __ldg((const float4*)&g_ne[tile * 8192 + slot * 4]);
                }
                __syncthreads();
                const float* wrow = &s_sc[g * N_NODES + tile * 128];
                #pragma unroll 4
                for (int nn = 0; nn < 128; nn++) {
                    float w = wrow[nn];
                    float2 nv = *(const float2*)&s_buf[nn * H + h0];
                    a0 = fmaf(w, nv.x, a0);
                    a1 = fmaf(w, nv.y, a1);
                }
                __syncthreads();
            }
            float inv = s_inv[g];
            s_ctx[g * H + h0]     = a0 * inv;
            s_ctx[g * H + h0 + 1] = a1 * inv;
        }
        __syncthreads();

        // ---- GRU gates (coalesced transposed weights) ----
        {
            float* s_gi = s_buf;           // [8][192]
            float* s_gh = s_buf + 1536;    // [8][192]
            #pragma unroll
            for (int p = 0; p < 2; p++) {
                int item = tid + p * 256;
                if (item < 384) {
                    int bi = item / 48;
                    int j0 = (item - bi * 48) * 4;
                    float i0 = 0.f, i1 = 0.f, i2 = 0.f, i3 = 0.f;
                    float h0a = 0.f, h1a = 0.f, h2a = 0.f, h3a = 0.f;
                    #pragma unroll 8
                    for (int k = 0; k < H; k++) {
                        float cv = s_ctx[bi * H + k];
                        float sv = s_s[bi * H + k];
                        float4 wi = __ldg((const float4*)(wiT + k * 192 + j0));
                        float4 wh = __ldg((const float4*)(whT + k * 192 + j0));
                        i0 = fmaf(cv, wi.x, i0); i1 = fmaf(cv, wi.y, i1);
                        i2 = fmaf(cv, wi.z, i2); i3 = fmaf(cv, wi.w, i3);
                        h0a = fmaf(sv, wh.x, h0a); h1a = fmaf(sv, wh.y, h1a);
                        h2a = fmaf(sv, wh.z, h2a); h3a = fmaf(sv, wh.w, h3a);
                    }
                    float4 b4i = __ldg((const float4*)(bih + c * 192 + j0));
                    float4 b4h = __ldg((const float4*)(bhh + c * 192 + j0));
                    float4 ri = make_float4(i0 + b4i.x, i1 + b4i.y, i2 + b4i.z, i3 + b4i.w);
                    float4 rh = make_float4(h0a + b4h.x, h1a + b4h.y, h2a + b4h.z, h3a + b4h.w);
                    *(float4*)&s_gi[bi * 192 + j0] = ri;
                    *(float4*)&s_gh[bi * 192 + j0] = rh;
                }
            }
            __syncthreads();
            float news[2];
            #pragma unroll
            for (int p = 0; p < 2; p++) {
                int i = tid + p * 256;
                int bi = i >> 6, h = i & 63;
                float r = fsigf(s_gi[bi * 192 + h] + s_gh[bi * 192 + h]);
                float z = fsigf(s_gi[bi * 192 + 64 + h] + s_gh[bi * 192 + 64 + h]);
                float cand = ftanhf(s_gi[bi * 192 + 128 + h] + r * s_gh[bi * 192 + 128 + h]);
                news[p] = (1.f - z) * cand + z * s_s[bi * H + h];
            }
            __syncthreads();
            #pragma unroll
            for (int p = 0; p < 2; p++) {
                int i = tid + p * 256;
                s_s[i] = news[p];
            }
        }
        __syncthreads();
    }

    #pragma unroll
    for (int p = 0; p < 2; p++) {
        int i = tid + p * 256;
        int bi = i >> 6, h = i & 63;
        int n = b0 + bi;
        float v = s_s[i];
        g_S[((size_t)c * N_NODES + n) * H + h] = v;
        out_stk[((size_t)n * C_CHAINS + c) * H + h] = v;
    }
}

// ---------------- epilogue ----------------
__global__ void k_final1(const float* __restrict__ Wag1, const float* __restrict__ bag1) {
    int idx = blockIdx.x * blockDim.x + threadIdx.x;
    int n = idx >> 6, j = idx & 63;
    float acc = bag1[j];
    for (int c = 0; c < C_CHAINS; c++) {
        const float* Sr = g_S + ((size_t)c * N_NODES + n) * H;
        const float* Wr = Wag1 + (size_t)c * H * H + j;
        #pragma unroll 8
        for (int h = 0; h < H; h++)
            acc = fmaf(Sr[h], Wr[(size_t)h * H], acc);
    }
    g_final1[idx] = fmaxf(acc, 0.f);
}

__global__ void k_final2(const float* __restrict__ Wag2, const float* __restrict__ bag2,
                         float* __restrict__ o_fin) {
    int idx = blockIdx.x * blockDim.x + threadIdx.x;
    int n = idx >> 6, j = idx & 63;
    float acc = bag2[j];
    #pragma unroll 8
    for (int k = 0; k < H; k++)
        acc = fmaf(g_final1[n * H + k], Wag2[k * H + j], acc);
    g_final[idx] = acc;
    o_fin[idx] = acc;
}

__global__ void k_attn(const float* __restrict__ Wp, const float* __restrict__ bp,
                       float* __restrict__ o_att, float* __restrict__ o_pred) {
    int gw = (blockIdx.x * blockDim.x + threadIdx.x) >> 5;
    int lane = threadIdx.x & 31;
    if (gw >= N_NODES) return;
    int n = gw;
    const float* fv = g_final + n * H;
    float dot = -1e30f;
    if (lane < C_CHAINS) {
        const float* Sv = g_S + ((size_t)lane * N_NODES + n) * H;
        float d = 0.f;
        #pragma unroll 8
        for (int h = 0; h < H; h++) d = fmaf(fv[h], Sv[h], d);
        dot = d;
    }
    float mx = dot;
    #pragma unroll
    for (int o = 16; o > 0; o >>= 1) mx = fmaxf(mx, __shfl_xor_sync(0xffffffffu, mx, o));
    float p = (lane < C_CHAINS) ? __expf(dot - mx) : 0.f;
    float smv = p;
    #pragma unroll
    for (int o = 16; o > 0; o >>= 1) smv += __shfl_xor_sync(0xffffffffu, smv, o);
    if (lane < C_CHAINS) o_att[n * C_CHAINS + lane] = __fdividef(p, smv);

    float ps = 0.f;
    for (int h = lane; h < H; h += 32) ps = fmaf(fv[h], Wp[h], ps);
    #pragma unroll
    for (int o = 16; o > 0; o >>= 1) ps += __shfl_xor_sync(0xffffffffu, ps, o);
    if (lane == 0) o_pred[n] = ps + bp[0];
}

// ---------------- launch ----------------
extern "C" void kernel_launch(void* const* d_in, const int* in_sizes, int n_in,
                              void* d_out, int out_size) {
    (void)in_sizes; (void)n_in; (void)out_size;
    const float* nf    = (const float*)d_in[0];
    const int*   edges = (const int*)d_in[1];
    const float* Wt1   = (const float*)d_in[2];
    const float* bt1   = (const float*)d_in[3];
    const float* Wt2   = (const float*)d_in[4];
    const float* bt2   = (const float*)d_in[5];
    const float* Wci   = (const float*)d_in[6];
    const float* bci   = (const float*)d_in[7];
    const float* Wa1   = (const float*)d_in[8];
    const float* ba1   = (const float*)d_in[9];
    const float* Wa2   = (const float*)d_in[10];
    const float* ba2   = (const float*)d_in[11];
    const float* Wih   = (const float*)d_in[12];
    const float* Whh   = (const float*)d_in[13];
    const float* bih   = (const float*)d_in[14];
    const float* bhh   = (const float*)d_in[15];
    const float* Wag1  = (const float*)d_in[16];
    const float* bag1  = (const float*)d_in[17];
    const float* Wag2  = (const float*)d_in[18];
    const float* bag2  = (const float*)d_in[19];
    const float* Wp    = (const float*)d_in[20];
    const float* bp    = (const float*)d_in[21];

    float* out    = (float*)d_out;
    float* o_stk  = out;
    float* o_fin  = out + (size_t)N_NODES * C_CHAINS * H;
    float* o_att  = o_fin + N_NODES * H;
    float* o_pred = o_att + N_NODES * C_CHAINS;

    static int smem_set = 0;
    const int SMEM_CHAIN = 18056 * 4;
    if (!smem_set) {
        cudaFuncSetAttribute(k_chain, cudaFuncAttributeMaxDynamicSharedMemorySize, SMEM_CHAIN);
        smem_set = 1;
    }

    k_mlp1<<<(N_NODES * H) / 256, 256>>>(nf, Wt1, bt1);
    k_mask_set<<<E_EDGES / 256, 256>>>(edges);
    k_mlp2<<<(N_NODES * H) / 256, 256>>>(Wt2, bt2);
    k_states0<<<(C_CHAINS * N_NODES * H) / 256, 256>>>(Wci, bci);
    k_npT<<<(C_CHAINS * H * N_NODES) / 256, 256>>>(Wa1);
    k_gruT<<<(C_CHAINS * H * 192) / 256, 256>>>(Wih, Whh);

    dim3 grid(N_NODES / BT, C_CHAINS);
    k_chain<<<grid, TPB, SMEM_CHAIN>>>(Wa1, ba1, Wa2, ba2, bih, bhh, o_stk);

    k_final1<<<(N_NODES * H) / 256, 256>>>(Wag1, bag1);
    k_final2<<<(N_NODES * H) / 256, 256>>>(Wag2, bag2, o_fin);
    k_attn<<<N_NODES / 8, 256>>>(Wp, bp, o_att, o_pred);
}

// round 3
// speedup vs baseline: 3.2755x; 1.0863x over previous
#include <cuda_runtime.h>
#include <math.h>

#define N_NODES 1024
#define D_IN    256
#define H       64
#define C_CHAINS 20
#define L_STEPS 3
#define E_EDGES 16384
#define BT      8
#define TPB     256

typedef unsigned long long ull;

// ---------------- scratch ----------------
__device__ __align__(16) float g_t1[N_NODES * H];
__device__ __align__(16) float g_ne[N_NODES * H];            // [n][h]
__device__ __align__(16) float g_neT[H * N_NODES];           // [h][n]
__device__ __align__(16) float g_mask[N_NODES];
__device__ __align__(16) float g_S[C_CHAINS * N_NODES * H];  // [c][n][h]
__device__ __align__(16) float g_npP[C_CHAINS * 32 * N_NODES * 2];   // [c][h2][n][2]
__device__ __align__(16) float g_WihP[C_CHAINS * 32 * 192 * 2];      // [c][k2][j][2]
__device__ __align__(16) float g_WhhP[C_CHAINS * 32 * 192 * 2];
__device__ __align__(16) float g_wsP[C_CHAINS * 32 * H * 2];         // [c][k2][h][2]
__device__ __align__(16) float g_final1[N_NODES * H];
__device__ __align__(16) float g_final[N_NODES * H];

// ---------------- f32x2 helpers (Blackwell packed fp32) ----------------
__device__ __forceinline__ ull pk(float lo, float hi) {
    ull r; asm("mov.b64 %0,{%1,%2};" : "=l"(r) : "f"(lo), "f"(hi)); return r;
}
__device__ __forceinline__ void upk(ull v, float& lo, float& hi) {
    asm("mov.b64 {%0,%1},%2;" : "=f"(lo), "=f"(hi) : "l"(v));
}
__device__ __forceinline__ ull add2(ull a, ull b) {
    ull r; asm("add.rn.f32x2 %0,%1,%2;" : "=l"(r) : "l"(a), "l"(b)); return r;
}
__device__ __forceinline__ ull fma2(ull a, ull b, ull c) {
    ull r; asm("fma.rn.f32x2 %0,%1,%2,%3;" : "=l"(r) : "l"(a), "l"(b), "l"(c)); return r;
}
__device__ __forceinline__ ull lds2(const float* p) {
    return *reinterpret_cast<const ull*>(p);
}

__device__ __forceinline__ float fsigf(float x) { return __fdividef(1.f, 1.f + __expf(-x)); }
__device__ __forceinline__ float ftanhf(float x) {
    x = fminf(fmaxf(x, -15.f), 15.f);
    float e = __expf(2.f * x);
    return __fdividef(e - 1.f, e + 1.f);
}

// ---------------- prologue ----------------
__global__ void k_mask_set(const int* __restrict__ edges) {
    int i = blockIdx.x * blockDim.x + threadIdx.x;
    if (i < E_EDGES) g_mask[edges[2 * i + 1]] = 1.0f;
}

__global__ void k_mlp1(const float* __restrict__ A, const float* __restrict__ W,
                       const float* __restrict__ b) {
    int idx = blockIdx.x * blockDim.x + threadIdx.x;
    if (idx < N_NODES) g_mask[idx] = 0.f;
    int n = idx >> 6, j = idx & 63;
    float acc = b[j];
    #pragma unroll 8
    for (int k = 0; k < D_IN; k++) acc = fmaf(A[n * D_IN + k], W[k * H + j], acc);
    g_t1[idx] = fmaxf(acc, 0.f);
}

__global__ void k_mlp2(const float* __restrict__ W, const float* __restrict__ b) {
    int idx = blockIdx.x * blockDim.x + threadIdx.x;
    int n = idx >> 6, j = idx & 63;
    float acc = b[j];
    #pragma unroll 8
    for (int k = 0; k < H; k++) acc = fmaf(g_t1[n * H + k], W[k * H + j], acc);
    float v = fmaxf(acc, 0.f);
    g_ne[idx] = v;
    g_neT[j * N_NODES + n] = v;
}

__global__ void k_states0(const float* __restrict__ Wci, const float* __restrict__ bci) {
    int idx = blockIdx.x * blockDim.x + threadIdx.x;
    int h = idx & 63;
    int n = (idx >> 6) & (N_NODES - 1);
    int c = idx >> 16;
    float acc = bci[c * H + h];
    #pragma unroll 8
    for (int k = 0; k < H; k++)
        acc = fmaf(g_ne[n * H + k], Wci[k * (C_CHAINS * H) + c * H + h], acc);
    g_S[idx] = acc;
}

// npP[c][h/2][n][h&1] = sum_k ne[n,k]*Wa1[c, H+k, h]
__global__ void k_npP(const float* __restrict__ Wa1) {
    int idx = blockIdx.x * blockDim.x + threadIdx.x;   // (c*H+h)*N + n
    int n = idx & (N_NODES - 1);
    int ch = idx >> 10;
    int h = ch & 63, c = ch >> 6;
    const float* W = Wa1 + c * 2 * H * H + H * H;
    float acc = 0.f;
    #pragma unroll 8
    for (int k = 0; k < H; k++)
        acc = fmaf(g_neT[k * N_NODES + n], W[k * H + h], acc);
    g_npP[((((size_t)c * 32) + (h >> 1)) * N_NODES + n) * 2 + (h & 1)] = acc;
}

// interleaved GRU weights: WihP[c][k/2][j][k&1] = Wih[c][j][k]
__global__ void k_gruP(const float* __restrict__ Wih, const float* __restrict__ Whh) {
    int idx = blockIdx.x * blockDim.x + threadIdx.x;   // c*12288 + k*192 + j
    int j = idx % 192;
    int t = idx / 192;
    int k = t & 63, c = t >> 6;
    int src = c * 12288 + j * H + k;
    int dst = ((c * 32 + (k >> 1)) * 192 + j) * 2 + (k & 1);
    g_WihP[dst] = Wih[src];
    g_WhhP[dst] = Whh[src];
}

// wsP[c][k/2][h][k&1] = Wa1[c][k][h]  (w_state)
__global__ void k_wsP(const float* __restrict__ Wa1) {
    int idx = blockIdx.x * blockDim.x + threadIdx.x;   // c*4096 + k*64 + h
    int h = idx & 63;
    int k = (idx >> 6) & 63;
    int c = idx >> 12;
    g_wsP[((c * 32 + (k >> 1)) * H + h) * 2 + (k & 1)] = Wa1[c * 2 * H * H + k * H + h];
}

// ---------------- main fused chain kernel ----------------
#define NE_PAD 132
__global__ void __launch_bounds__(TPB, 2) k_chain(
    const float* __restrict__ ba1, const float* __restrict__ Wa2,
    const float* __restrict__ ba2,
    const float* __restrict__ bih, const float* __restrict__ bhh,
    float* __restrict__ out_stk)
{
    const int c = blockIdx.y;
    const int b0 = blockIdx.x * BT;
    const int tid = threadIdx.x;

    extern __shared__ float sm[];
    float* s_sc  = sm;              // [8][1024]
    float* s_big = sm + 8192;       // neT tile [64][NE_PAD] | s_part[8][512] | gates
    float* s_s   = sm + 16640;      // [8][64]
    float* s_pre = sm + 17152;
    float* s_ctx = sm + 17664;
    float* s_wa2 = sm + 18176;
    float* s_ba1 = sm + 18240;
    float* s_inv = sm + 18304;      // [8]

    if (tid < H) { s_wa2[tid] = Wa2[c * H + tid]; s_ba1[tid] = ba1[c * H + tid]; }
    const float ba2c = ba2[c];
    #pragma unroll
    for (int p = 0; p < 2; p++) {
        int i = tid + p * 256;
        int bi = i >> 6, h = i & 63;
        s_s[i] = g_S[((size_t)c * N_NODES + b0 + bi) * H + h];
    }
    __syncthreads();

    const float* npP = g_npP + (size_t)c * 32 * N_NODES * 2;
    const float* wsP = g_wsP + (size_t)c * 32 * H * 2;
    const float* wiP = g_WihP + (size_t)c * 32 * 192 * 2;
    const float* whP = g_WhhP + (size_t)c * 32 * 192 * 2;

    const int wpid = tid >> 5, lane = tid & 31;

    for (int t = 0; t < L_STEPS; t++) {
        // ---- pre = s @ w_state + ba1 (k-paired f32x2) ----
        #pragma unroll
        for (int p = 0; p < 2; p++) {
            int i = tid + p * 256;
            int bi = i >> 6, h = i & 63;
            ull acc = 0;
            #pragma unroll 8
            for (int k2 = 0; k2 < 32; k2++) {
                ull s2 = lds2(&s_s[bi * H + k2 * 2]);
                ull w2 = __ldg((const ull*)(wsP + ((size_t)k2 * H + h) * 2));
                acc = fma2(s2, w2, acc);
            }
            float lo, hi; upk(acc, lo, hi);
            s_pre[i] = lo + hi + s_ba1[h];
        }
        __syncthreads();

        // ---- scores: h-paired f32x2, two n-chunks of 2 n each ----
        #pragma unroll
        for (int chunk = 0; chunk < 2; chunk++) {
            const int n0 = chunk * 512 + tid * 2;
            ull acc0[BT], acc1[BT];
            #pragma unroll
            for (int bi = 0; bi < BT; bi++) { acc0[bi] = 0; acc1[bi] = 0; }
            ulonglong2 vv = __ldg((const ulonglong2*)(npP + (size_t)n0 * 2));
            for (int h2 = 0; h2 < 32; h2++) {
                ulonglong2 nv;
                if (h2 < 31)
                    nv = __ldg((const ulonglong2*)(npP + ((size_t)(h2 + 1) * N_NODES + n0) * 2));
                ull ww = lds2(&s_wa2[h2 * 2]);
                #pragma unroll
                for (int bi = 0; bi < BT; bi++) {
                    ull pp = lds2(&s_pre[bi * H + h2 * 2]);
                    ull ta = add2(pp, vv.x);
                    ull tb = add2(pp, vv.y);
                    float a, b, e, f;
                    upk(ta, a, b); upk(tb, e, f);
                    a = fmaxf(a, 0.f); b = fmaxf(b, 0.f);
                    e = fmaxf(e, 0.f); f = fmaxf(f, 0.f);
                    acc0[bi] = fma2(ww, pk(a, b), acc0[bi]);
                    acc1[bi] = fma2(ww, pk(e, f), acc1[bi]);
                }
                vv = nv;
            }
            const float2 m2 = *(const float2*)&g_mask[n0];
            #pragma unroll
            for (int bi = 0; bi < BT; bi++) {
                float l0, h0v, l1, h1v;
                upk(acc0[bi], l0, h0v);
                upk(acc1[bi], l1, h1v);
                float2 r;
                r.x = (l0 + h0v + ba2c) * m2.x;
                r.y = (l1 + h1v + ba2c) * m2.y;
                *(float2*)&s_sc[bi * N_NODES + n0] = r;
            }
        }
        __syncthreads();

        // ---- row softmax (warp per row) ----
        {
            float mx = -1e30f;
            #pragma unroll 4
            for (int n = lane; n < N_NODES; n += 32) mx = fmaxf(mx, s_sc[wpid * N_NODES + n]);
            #pragma unroll
            for (int o = 16; o > 0; o >>= 1) mx = fmaxf(mx, __shfl_xor_sync(0xffffffffu, mx, o));
            float smv = 0.f;
            #pragma unroll 4
            for (int n = lane; n < N_NODES; n += 32) {
                float p = __expf(s_sc[wpid * N_NODES + n] - mx);
                s_sc[wpid * N_NODES + n] = p;
                smv += p;
            }
            #pragma unroll
            for (int o = 16; o > 0; o >>= 1) smv += __shfl_xor_sync(0xffffffffu, smv, o);
            if (lane == 0) s_inv[wpid] = __fdividef(1.f, smv);
        }
        __syncthreads();

        // ---- ctx: n-paired f32x2; warp handles all 8 rows on its n-slice ----
        {
            const int h0 = lane * 2;
            ull accA[BT], accB[BT];
            #pragma unroll
            for (int r = 0; r < BT; r++) { accA[r] = 0; accB[r] = 0; }

            for (int tile = 0; tile < N_NODES / 128; tile++) {
                // stage transposed ne tile [64][128] (pad 132)
                #pragma unroll
                for (int v = 0; v < 8; v++) {
                    int slot = tid + v * 256;        // 2048 float4 slots
                    int row = slot >> 5, j4 = (slot & 31) * 4;
                    *(float4*)&s_big[row * NE_PAD + j4] =
                        __ldg((const float4*)&g_neT[row * N_NODES + tile * 128 + j4]);
                }
                __syncthreads();
                // warp's 8 nn-pairs in this tile
                #pragma unroll 2
                for (int pp2 = 0; pp2 < 8; pp2++) {
                    const int np0 = (wpid * 8 + pp2) * 2;        // within tile
                    ull ne0 = lds2(&s_big[h0 * NE_PAD + np0]);
                    ull ne1 = lds2(&s_big[(h0 + 1) * NE_PAD + np0]);
                    #pragma unroll
                    for (int r = 0; r < BT; r++) {
                        ull ww = lds2(&s_sc[r * N_NODES + tile * 128 + np0]);
                        accA[r] = fma2(ww, ne0, accA[r]);
                        accB[r] = fma2(ww, ne1, accB[r]);
                    }
                }
                __syncthreads();
            }
            // cross-warp reduce through s_big (aliases tile buffer)
            float* s_part = s_big;     // [8 warps][512]
            #pragma unroll
            for (int r = 0; r < BT; r++) {
                float la, ha, lb, hb;
                upk(accA[r], la, ha); upk(accB[r], lb, hb);
                s_part[wpid * 512 + r * H + h0]     = la + ha;
                s_part[wpid * 512 + r * H + h0 + 1] = lb + hb;
            }
            __syncthreads();
            #pragma unroll
            for (int v = 0; v < 2; v++) {
                int s = tid + v * 256;
                float sum = 0.f;
                #pragma unroll
                for (int w = 0; w < 8; w++) sum += s_part[w * 512 + s];
                s_ctx[s] = sum * s_inv[s >> 6];
            }
        }
        __syncthreads();

        // ---- GRU gates (k-paired f32x2, interleaved weights) ----
        {
            float* s_gi = s_big;           // [8][192]
            float* s_gh = s_big + 1536;
            #pragma unroll
            for (int p = 0; p < 2; p++) {
                int item = tid + p * 256;
                if (item < 384) {
                    int bi = item / 48;
                    int j0 = (item - bi * 48) * 4;
                    ull ai0 = 0, ai1 = 0, ai2 = 0, ai3 = 0;
                    ull ah0 = 0, ah1 = 0, ah2 = 0, ah3 = 0;
                    #pragma unroll 4
                    for (int k2 = 0; k2 < 32; k2++) {
                        ull cv2 = lds2(&s_ctx[bi * H + k2 * 2]);
                        ull sv2 = lds2(&s_s[bi * H + k2 * 2]);
                        const float* wip = wiP + ((size_t)k2 * 192 + j0) * 2;
                        const float* whp = whP + ((size_t)k2 * 192 + j0) * 2;
                        ulonglong2 wiA = __ldg((const ulonglong2*)wip);
                        ulonglong2 wiB = __ldg((const ulonglong2*)(wip + 4));
                        ulonglong2 whA = __ldg((const ulonglong2*)whp);
                        ulonglong2 whB = __ldg((const ulonglong2*)(whp + 4));
                        ai0 = fma2(cv2, wiA.x, ai0); ai1 = fma2(cv2, wiA.y, ai1);
                        ai2 = fma2(cv2, wiB.x, ai2); ai3 = fma2(cv2, wiB.y, ai3);
                        ah0 = fma2(sv2, whA.x, ah0); ah1 = fma2(sv2, whA.y, ah1);
                        ah2 = fma2(sv2, whB.x, ah2); ah3 = fma2(sv2, whB.y, ah3);
                    }
                    float4 b4i = __ldg((const float4*)(bih + c * 192 + j0));
                    float4 b4h = __ldg((const float4*)(bhh + c * 192 + j0));
                    float l, hv;
                    float4 ri, rh;
                    upk(ai0, l, hv); ri.x = l + hv + b4i.x;
                    upk(ai1, l, hv); ri.y = l + hv + b4i.y;
                    upk(ai2, l, hv); ri.z = l + hv + b4i.z;
                    upk(ai3, l, hv); ri.w = l + hv + b4i.w;
                    upk(ah0, l, hv); rh.x = l + hv + b4h.x;
                    upk(ah1, l, hv); rh.y = l + hv + b4h.y;
                    upk(ah2, l, hv); rh.z = l + hv + b4h.z;
                    upk(ah3, l, hv); rh.w = l + hv + b4h.w;
                    *(float4*)&s_gi[bi * 192 + j0] = ri;
                    *(float4*)&s_gh[bi * 192 + j0] = rh;
                }
            }
            __syncthreads();
            float news[2];
            #pragma unroll
            for (int p = 0; p < 2; p++) {
                int i = tid + p * 256;
                int bi = i >> 6, h = i & 63;
                float r = fsigf(s_gi[bi * 192 + h] + s_gh[bi * 192 + h]);
                float z = fsigf(s_gi[bi * 192 + 64 + h] + s_gh[bi * 192 + 64 + h]);
                float cand = ftanhf(s_gi[bi * 192 + 128 + h] + r * s_gh[bi * 192 + 128 + h]);
                news[p] = (1.f - z) * cand + z * s_s[bi * H + h];
            }
            __syncthreads();
            #pragma unroll
            for (int p = 0; p < 2; p++) {
                int i = tid + p * 256;
                s_s[i] = news[p];
            }
        }
        __syncthreads();
    }

    #pragma unroll
    for (int p = 0; p < 2; p++) {
        int i = tid + p * 256;
        int bi = i >> 6, h = i & 63;
        int n = b0 + bi;
        float v = s_s[i];
        g_S[((size_t)c * N_NODES + n) * H + h] = v;
        out_stk[((size_t)n * C_CHAINS + c) * H + h] = v;
    }
}

// ---------------- epilogue ----------------
__global__ void k_final1(const float* __restrict__ Wag1, const float* __restrict__ bag1) {
    int idx = blockIdx.x * blockDim.x + threadIdx.x;
    int n = idx >> 6, j = idx & 63;
    float acc = bag1[j];
    for (int c = 0; c < C_CHAINS; c++) {
        const float* Sr = g_S + ((size_t)c * N_NODES + n) * H;
        const float* Wr = Wag1 + (size_t)c * H * H + j;
        #pragma unroll 8
        for (int h = 0; h < H; h++)
            acc = fmaf(Sr[h], Wr[(size_t)h * H], acc);
    }
    g_final1[idx] = fmaxf(acc, 0.f);
}

__global__ void k_final2(const float* __restrict__ Wag2, const float* __restrict__ bag2,
                         float* __restrict__ o_fin) {
    int idx = blockIdx.x * blockDim.x + threadIdx.x;
    int n = idx >> 6, j = idx & 63;
    float acc = bag2[j];
    #pragma unroll 8
    for (int k = 0; k < H; k++)
        acc = fmaf(g_final1[n * H + k], Wag2[k * H + j], acc);
    g_final[idx] = acc;
    o_fin[idx] = acc;
}

__global__ void k_attn(const float* __restrict__ Wp, const float* __restrict__ bp,
                       float* __restrict__ o_att, float* __restrict__ o_pred) {
    int gw = (blockIdx.x * blockDim.x + threadIdx.x) >> 5;
    int lane = threadIdx.x & 31;
    if (gw >= N_NODES) return;
    int n = gw;
    const float* fv = g_final + n * H;
    float dot = -1e30f;
    if (lane < C_CHAINS) {
        const float* Sv = g_S + ((size_t)lane * N_NODES + n) * H;
        float d = 0.f;
        #pragma unroll 8
        for (int h = 0; h < H; h++) d = fmaf(fv[h], Sv[h], d);
        dot = d;
    }
    float mx = dot;
    #pragma unroll
    for (int o = 16; o > 0; o >>= 1) mx = fmaxf(mx, __shfl_xor_sync(0xffffffffu, mx, o));
    float p = (lane < C_CHAINS) ? __expf(dot - mx) : 0.f;
    float smv = p;
    #pragma unroll
    for (int o = 16; o > 0; o >>= 1) smv += __shfl_xor_sync(0xffffffffu, smv, o);
    if (lane < C_CHAINS) o_att[n * C_CHAINS + lane] = __fdividef(p, smv);

    float ps = 0.f;
    for (int h = lane; h < H; h += 32) ps = fmaf(fv[h], Wp[h], ps);
    #pragma unroll
    for (int o = 16; o > 0; o >>= 1) ps += __shfl_xor_sync(0xffffffffu, ps, o);
    if (lane == 0) o_pred[n] = ps + bp[0];
}

// ---------------- launch ----------------
extern "C" void kernel_launch(void* const* d_in, const int* in_sizes, int n_in,
                              void* d_out, int out_size) {
    (void)in_sizes; (void)n_in; (void)out_size;
    const float* nf    = (const float*)d_in[0];
    const int*   edges = (const int*)d_in[1];
    const float* Wt1   = (const float*)d_in[2];
    const float* bt1   = (const float*)d_in[3];
    const float* Wt2   = (const float*)d_in[4];
    const float* bt2   = (const float*)d_in[5];
    const float* Wci   = (const float*)d_in[6];
    const float* bci   = (const float*)d_in[7];
    const float* Wa1   = (const float*)d_in[8];
    const float* ba1   = (const float*)d_in[9];
    const float* Wa2   = (const float*)d_in[10];
    const float* ba2   = (const float*)d_in[11];
    const float* Wih   = (const float*)d_in[12];
    const float* Whh   = (const float*)d_in[13];
    const float* bih   = (const float*)d_in[14];
    const float* bhh   = (const float*)d_in[15];
    const float* Wag1  = (const float*)d_in[16];
    const float* bag1  = (const float*)d_in[17];
    const float* Wag2  = (const float*)d_in[18];
    const float* bag2  = (const float*)d_in[19];
    const float* Wp    = (const float*)d_in[20];
    const float* bp    = (const float*)d_in[21];

    float* out    = (float*)d_out;
    float* o_stk  = out;
    float* o_fin  = out + (size_t)N_NODES * C_CHAINS * H;
    float* o_att  = o_fin + N_NODES * H;
    float* o_pred = o_att + N_NODES * C_CHAINS;

    static int smem_set = 0;
    const int SMEM_CHAIN = 18312 * 4;
    if (!smem_set) {
        cudaFuncSetAttribute(k_chain, cudaFuncAttributeMaxDynamicSharedMemorySize, SMEM_CHAIN);
        smem_set = 1;
    }

    k_mlp1<<<(N_NODES * H) / 256, 256>>>(nf, Wt1, bt1);
    k_mask_set<<<E_EDGES / 256, 256>>>(edges);
    k_mlp2<<<(N_NODES * H) / 256, 256>>>(Wt2, bt2);
    k_states0<<<(C_CHAINS * N_NODES * H) / 256, 256>>>(Wci, bci);
    k_npP<<<(C_CHAINS * H * N_NODES) / 256, 256>>>(Wa1);
    k_gruP<<<(C_CHAINS * H * 192) / 256, 256>>>(Wih, Whh);
    k_wsP<<<(C_CHAINS * H * H) / 256, 256>>>(Wa1);

    dim3 grid(N_NODES / BT, C_CHAINS);
    k_chain<<<grid, TPB, SMEM_CHAIN>>>(ba1, Wa2, ba2, bih, bhh, o_stk);

    k_final1<<<(N_NODES * H) / 256, 256>>>(Wag1, bag1);
    k_final2<<<(N_NODES * H) / 256, 256>>>(Wag2, bag2, o_fin);
    k_attn<<<N_NODES / 8, 256>>>(Wp, bp, o_att, o_pred);
}